// round 10
// baseline (speedup 1.0000x reference)
#include <cuda_runtime.h>
#include <math.h>

#define NB 8
#define NT 8192
#define ND 2048
#define NROWS (NB * NT)
#define KSEL 2048          // NT * 0.25
#define GRID 592           // 4 CTAs/SM x 148 SMs (co-residency proven; see audit)
#define NWARPS (GRID * 8)  // 4736 worker warps
#define MAXIT 14           // ceil(NROWS / NWARPS)
#define GATE_CTAS 256
#define CAND_MAX 256

// Device-global scratch (no allocations). Barrier counts self-reset;
// generations are monotonic -> graph-replay safe.
__device__ double   d_ea[NROWS];
__device__ double   d_eb0[NROWS];
__device__ double   d_part[GRID];
__device__ unsigned d_cnt[2];
__device__ unsigned d_gen[2];

// Fast fp64 exp: Cody-Waite + 13-term poly, ~1e-15 rel err (R6/R7: final
// fp32 g bits identical to libm path; ordering gaps near k-th are ~1e-5).
__device__ __forceinline__ double fast_exp(double x)
{
    x = fmin(fmax(x, -700.0), 700.0);
    double k = rint(x * 1.4426950408889634074);
    double r = fma(-k, 6.93147180369123816490e-01, x);
    r = fma(-k, 1.90821492927058770002e-10, r);
    double p = 2.08767569878681e-09;
    p = fma(p, r, 2.50521083854417e-08);
    p = fma(p, r, 2.75573192239859e-07);
    p = fma(p, r, 2.75573192239859e-06);
    p = fma(p, r, 2.48015873015873e-05);
    p = fma(p, r, 1.98412698412698e-04);
    p = fma(p, r, 1.38888888888889e-03);
    p = fma(p, r, 8.33333333333333e-03);
    p = fma(p, r, 4.16666666666667e-02);
    p = fma(p, r, 1.66666666666667e-01);
    p = fma(p, r, 0.5);
    p = fma(p, r, 1.0);
    p = fma(p, r, 1.0);
    return p * __longlong_as_double((unsigned long long)((long long)k + 1023) << 52);
}

// ---------------------------------------------------------------------------
// Single persistent kernel.
//  A) warp-per-row squared-norm reduction over the full 1.07 GB (the runtime),
//     per-row fp64 exps batched lane-parallel in a CTA tail (hidden under
//     memory stalls), per-CTA fp64 partial sum of D_st.
//  bar0 (592 arrivals; only CTAs <256 wait) -> redundant partials-reduce -> K.
//  B) gate: g = (1+ea+eb)/(1+ea+eb+ea*eb), Newton-recip division, 64K elems.
//  bar1 (256 arrivals; only CTAs <8 wait) -> per-batch exact top-k on smem
//     keys (2 radix passes + candidate rank-count; exact fallback), mask.
// Deadlock-safety: spinners(bar0) <= 256, spinners(bar1) <= 8; all other CTAs
// arrive-and-exit freeing slots; occupancy >= 4/SM (launch_bounds) >> needed.
// ---------------------------------------------------------------------------
__global__ void __launch_bounds__(256, 4) mega_kernel(
    const float4* __restrict__ a, const float4* __restrict__ p,
    const float* __restrict__ oce, const float* __restrict__ mcu,
    const float* __restrict__ bce, const float* __restrict__ bcu,
    float* __restrict__ out)
{
    __shared__ unsigned s_keys[NT];        // 32 KB (select phase)
    __shared__ int      s_hist[8 * 256];   // 8 KB  (select phase)
    __shared__ float2   s_stash[8 * MAXIT];
    __shared__ double   s_dsum[8];
    __shared__ double   s_red[8];
    __shared__ double   s_ma;
    __shared__ int      s_warp_tot[8];
    __shared__ unsigned s_pref, s_thresh;
    __shared__ int      s_remk, s_ce, s_c2, s_cnt, s_need, s_ceq;
    __shared__ unsigned s_cand[CAND_MAX];

    const int tid  = threadIdx.x;
    const int warp = tid >> 5;
    const int lane = tid & 31;
    const int cta  = blockIdx.x;

    // ---------------- Phase A: row reductions ----------------
    const int gw = cta * 8 + warp;
    double dsum = 0.0;
    int nr = 0;
    for (int r = gw; r < NROWS; r += NWARPS, ++nr) {
        const size_t base = (size_t)r * (ND / 4);
        float s_st = 0.0f, s_ch = 0.0f;
#pragma unroll
        for (int j = 0; j < 16; ++j) {
            float4 av = __ldg(&a[base + lane + 32 * j]);
            float4 pv = __ldg(&p[base + lane + 32 * j]);
            s_st += av.x * av.x + av.y * av.y + av.z * av.z + av.w * av.w;
            float dx = av.x - pv.x, dy = av.y - pv.y;
            float dz = av.z - pv.z, dw = av.w - pv.w;
            s_ch += dx * dx + dy * dy + dz * dz + dw * dw;
        }
#pragma unroll
        for (int off = 16; off > 0; off >>= 1) {
            s_st += __shfl_down_sync(0xFFFFFFFFu, s_st, off);
            s_ch += __shfl_down_sync(0xFFFFFFFFu, s_ch, off);
        }
        if (lane == 0) {
            const float invd = 1.0f / (float)ND;
            const float dst = s_st * invd;
            s_stash[warp * MAXIT + nr] = make_float2(dst, s_ch * invd);
            dsum += (double)dst;
        }
    }
    if (lane == 0) s_dsum[warp] = dsum;
    __syncthreads();

    // scalar params (fp32, uniform, cheap)
    const float xce = bce[0], xcu = bcu[0];
    const float bce_p = fmaxf(xce, 0.0f) + log1pf(expf(-fabsf(xce)));
    const float bcu_p = fmaxf(xcu, 0.0f) + log1pf(expf(-fabsf(xcu)));
    const float logoce = logf(oce[0] + 1e-10f);

    // lane-parallel exp tail: one thread per (warp, iter) row slot
    if (tid < 8 * MAXIT) {
        const int w = tid / MAXIT, i = tid % MAXIT;
        const int r = cta * 8 + w + i * NWARPS;
        if (r < NROWS) {
            const float2 dd = s_stash[w * MAXIT + i];
            const double CE = (double)dd.x - ((double)dd.y - (double)logoce);
            d_ea[r]  = fast_exp(-(double)bce_p * CE);
            d_eb0[r] = fast_exp(-(double)bcu_p * (double)dd.x);
        }
    }
    if (tid == 0) {
        double ps = 0.0;
#pragma unroll
        for (int i = 0; i < 8; ++i) ps += s_dsum[i];
        d_part[cta] = ps;
    }

    // ---------------- barrier 0 (592 arrivals; gate CTAs wait) ----------------
    __syncthreads();
    if (tid == 0) {
        __threadfence();                       // release d_ea/d_eb0/d_part
        const unsigned g0 = *(volatile unsigned*)&d_gen[0];
        const unsigned c  = atomicAdd(&d_cnt[0], 1u);
        if (c == GRID - 1) {
            d_cnt[0] = 0;
            __threadfence();
            atomicAdd(&d_gen[0], 1u);
        } else if (cta < GATE_CTAS) {
            while (*(volatile unsigned*)&d_gen[0] == g0) __nanosleep(128);
        }
        __threadfence();                       // acquire
    }
    __syncthreads();
    if (cta >= GATE_CTAS) return;              // arrived; slot freed

    // ---------------- mean -> K (redundant, fixed order, deterministic) ----
    {
        double v = 0.0;
        if (tid < GRID - 512)      v = (__ldcg(&d_part[tid]) + __ldcg(&d_part[tid + 256])) + __ldcg(&d_part[tid + 512]);
        else if (tid < GRID - 256) v =  __ldcg(&d_part[tid]) + __ldcg(&d_part[tid + 256]);
        else                       v =  __ldcg(&d_part[tid]);
#pragma unroll
        for (int off = 16; off > 0; off >>= 1)
            v += __shfl_down_sync(0xFFFFFFFFu, v, off);
        if (lane == 0) s_red[warp] = v;
        __syncthreads();
        if (tid == 0) {
            double tot = 0.0;
#pragma unroll
            for (int i = 0; i < 8; ++i) tot += s_red[i];
            s_ma = tot / (double)NROWS;
        }
        __syncthreads();
    }
    const double K = fast_exp((double)bcu_p * (double)mcu[0] * s_ma);

    // ---------------- Phase B: gate (64K elems over 256 CTAs) ----------------
    {
        const int idx = cta * 256 + tid;
        const double ea   = __ldcg(&d_ea[idx]);
        const double eb   = __ldcg(&d_eb0[idx]) * K;
        const double num  = 1.0 + ea + eb;
        const double den  = num + ea * eb;
        double rcp = (double)__frcp_rn((float)den);
        rcp = fma(fma(-den, rcp, 1.0), rcp, rcp);   // Newton 1
        rcp = fma(fma(-den, rcp, 1.0), rcp, rcp);   // Newton 2 -> ~0.5 ulp
        out[idx] = (float)(num * rcp);
    }

    // ---------------- barrier 1 (256 arrivals; CTAs <8 wait) ----------------
    __syncthreads();
    if (tid == 0) {
        __threadfence();                       // release g writes
        const unsigned g0 = *(volatile unsigned*)&d_gen[1];
        const unsigned c  = atomicAdd(&d_cnt[1], 1u);
        if (c == GATE_CTAS - 1) {
            d_cnt[1] = 0;
            __threadfence();
            atomicAdd(&d_gen[1], 1u);
        } else if (cta < NB) {
            while (*(volatile unsigned*)&d_gen[1] == g0) __nanosleep(128);
        }
        __threadfence();                       // acquire
    }
    __syncthreads();
    if (cta >= NB) return;

    // ---------------- Phase C: per-batch exact top-k (CTA b = batch b) ------
    const int b = cta;
    const float* gb = out + b * NT;
#pragma unroll
    for (int k = 0; k < 32; ++k)
        s_keys[tid + k * 256] = __float_as_uint(__ldcg(&gb[tid + k * 256]));
#pragma unroll
    for (int i = 0; i < 8; ++i) s_hist[tid + i * 256] = 0;
    if (tid == 0) { s_pref = 0u; s_remk = KSEL; s_ce = 0; s_c2 = 0; s_cnt = 0; }
    __syncthreads();

    // two radix passes over the top two bytes
    for (int shift = 24; shift >= 16; shift -= 8) {
        const unsigned pref = s_pref;
        const int remk = s_remk;
        const unsigned msk = (shift == 24) ? 0u : 0xFF000000u;

        int* myhist = s_hist + warp * 256;
#pragma unroll
        for (int k = 0; k < 32; ++k) {
            const unsigned u = s_keys[tid + k * 256];
            const bool ok = ((u & msk) == pref);
            const int bin = (u >> shift) & 0xFF;
            const unsigned active = __ballot_sync(0xFFFFFFFFu, ok);
            if (ok) {
                const unsigned peers = __match_any_sync(active, bin);
                if (lane == (__ffs(peers) - 1))
                    myhist[bin] += __popc(peers);
            }
        }
        __syncthreads();

        // row-sum + suffix scan: thread t owns bin r = 255 - t
        int v = 0;
#pragma unroll
        for (int w = 0; w < 8; ++w) v += s_hist[w * 256 + (255 - tid)];
        int x = v;
#pragma unroll
        for (int off = 1; off < 32; off <<= 1) {
            const int y = __shfl_up_sync(0xFFFFFFFFu, x, off);
            if (lane >= off) x += y;
        }
        if (lane == 31) s_warp_tot[warp] = x;
        __syncthreads();
        {
            int offset = 0;
            for (int w = 0; w < warp; ++w) offset += s_warp_tot[w];
            const int cum  = x + offset;
            const int prev = cum - v;
            if (prev < remk && cum >= remk) {
                s_pref = pref | ((unsigned)(255 - tid) << shift);
                s_remk = remk - prev;
                if (shift == 16) s_c2 = v;
            }
        }
#pragma unroll
        for (int i = 0; i < 8; ++i) s_hist[tid + i * 256] = 0;
        __syncthreads();
    }

    const int c2 = s_c2;
    const int remk2 = s_remk;
    const unsigned pref2 = s_pref;

    if (c2 <= CAND_MAX) {
        // gather prefix-matching candidates, rank-count the exact threshold
#pragma unroll
        for (int k = 0; k < 32; ++k) {
            const unsigned u = s_keys[tid + k * 256];
            if ((u & 0xFFFF0000u) == pref2) {
                const int pos = atomicAdd(&s_cnt, 1);
                if (pos < CAND_MAX) s_cand[pos] = u;
            }
        }
        __syncthreads();
        if (tid < c2) {
            const unsigned vi = s_cand[tid];
            int greater = 0, equal = 0;
            for (int j = 0; j < c2; ++j) {
                const unsigned vj = s_cand[j];
                greater += (vj > vi);
                equal   += (vj == vi);
            }
            if (greater < remk2 && remk2 <= greater + equal) {
                s_thresh = vi; s_need = remk2 - greater; s_ceq = equal;
            }
        }
        __syncthreads();
    } else {
        // exact fallback: remaining byte passes (hist already zeroed)
        for (int shift = 8; shift >= 0; shift -= 8) {
            const unsigned pref = s_pref;
            const int remk = s_remk;
            const unsigned msk = 0xFFFFFFFFu << (shift + 8);

            int* myhist = s_hist + warp * 256;
#pragma unroll
            for (int k = 0; k < 32; ++k) {
                const unsigned u = s_keys[tid + k * 256];
                const bool ok = ((u & msk) == pref);
                const int bin = (u >> shift) & 0xFF;
                const unsigned active = __ballot_sync(0xFFFFFFFFu, ok);
                if (ok) {
                    const unsigned peers = __match_any_sync(active, bin);
                    if (lane == (__ffs(peers) - 1))
                        myhist[bin] += __popc(peers);
                }
            }
            __syncthreads();

            int v = 0;
#pragma unroll
            for (int w = 0; w < 8; ++w) v += s_hist[w * 256 + (255 - tid)];
            int x = v;
#pragma unroll
            for (int off = 1; off < 32; off <<= 1) {
                const int y = __shfl_up_sync(0xFFFFFFFFu, x, off);
                if (lane >= off) x += y;
            }
            if (lane == 31) s_warp_tot[warp] = x;
            __syncthreads();
            {
                int offset = 0;
                for (int w = 0; w < warp; ++w) offset += s_warp_tot[w];
                const int cum  = x + offset;
                const int prev = cum - v;
                if (prev < remk && cum >= remk) {
                    s_pref = pref | ((unsigned)(255 - tid) << shift);
                    s_remk = remk - prev;
                    if (shift == 0) s_ce = v;
                }
            }
            if (shift > 0) {
#pragma unroll
                for (int i = 0; i < 8; ++i) s_hist[tid + i * 256] = 0;
            }
            __syncthreads();
        }
        if (tid == 0) { s_thresh = s_pref; s_need = s_remk; s_ceq = s_ce; }
        __syncthreads();
    }

    const unsigned thresh = s_thresh;
    const int need_eq = s_need;
    const int c_eq = s_ceq;

    // write binary mask (second output half)
    float* mout = out + NROWS + b * NT;
#pragma unroll
    for (int k = 0; k < 32; ++k) {
        const int i = tid + k * 256;
        const unsigned u = s_keys[i];
        float mval;
        if (u > thresh)      mval = 1.0f;
        else if (u < thresh) mval = 0.0f;
        else if (c_eq == need_eq) mval = 1.0f;      // no over-tie (common)
        else {
            // rare exact fp32 tie: lower index wins (jax.lax.top_k)
            int rnk = 0;
            for (int j = 0; j < i; ++j) if (s_keys[j] == thresh) ++rnk;
            mval = (rnk < need_eq) ? 1.0f : 0.0f;
        }
        mout[i] = mval;
    }
}

// ---------------------------------------------------------------------------
extern "C" void kernel_launch(void* const* d_in, const int* in_sizes, int n_in,
                              void* d_out, int out_size)
{
    const float4* a = (const float4*)d_in[0];   // actual_residual   [8,8192,2048] f32
    const float4* p = (const float4*)d_in[1];   // predicted_residual[8,8192,2048] f32
    const float* oce = (const float*)d_in[2];
    const float* mcu = (const float*)d_in[3];
    const float* bce = (const float*)d_in[4];
    const float* bcu = (const float*)d_in[5];
    float* out = (float*)d_out;                  // [2, 8, 8192]: g then binary mask

    mega_kernel<<<GRID, 256>>>(a, p, oce, mcu, bce, bcu, out);
}